// round 5
// baseline (speedup 1.0000x reference)
#include <cuda_runtime.h>

#define NRK 4
#define DW  64
#define KD  256          // NR*D plane stride
#define PAD 2048         // power-of-2 pad for bitonic (Nt <= 2048)
#define THREADS 512
#define PER 4            // sort elements per thread (PAD/THREADS)
#define NX  4            // search slots per thread (THREADS*NX >= Ns)
#define ALM_BLOCKS 8
#define NMAX 2048        // padded column stride
#define TOTAL_BLOCKS (KD + ALM_BLOCKS)

// Static scratch (no allocation allowed). Zero-initialized at load; transpose
// rewrites the same data every replay -> deterministic.
__device__ float  g_sT[KD * NMAX];          // s transposed+padded: [KD][NMAX]
__device__ float  g_tT[KD * NMAX];          // t transposed+padded: [KD][NMAX]
__device__ double g_col[KD];                // per-column all-pairs partial
__device__ double g_almp[ALM_BLOCKS * NRK]; // per-block per-k anchor partials
__device__ int    g_count = 0;              // completion ticket (self-resetting)

// ---------------- tiled transpose: [N][256] -> [256][NMAX] ----------------
__global__ void transpose_kernel(const float* __restrict__ s,
                                 const float* __restrict__ t,
                                 int Ns, int Nt) {
    __shared__ float tile[32][33];
    const float* src; float* dst; int N;
    if (blockIdx.z == 0) { src = s; dst = g_sT; N = Ns; }
    else                 { src = t; dst = g_tT; N = Nt; }
    const int tx = threadIdx.x, ty = threadIdx.y;  // 32 x 8
    const int r0 = blockIdx.x * 32, c0 = blockIdx.y * 32;
    #pragma unroll
    for (int i = 0; i < 4; i++) {
        int r = r0 + ty + i * 8;
        if (r < N) tile[ty + i * 8][tx] = src[r * KD + c0 + tx];
    }
    __syncthreads();
    #pragma unroll
    for (int i = 0; i < 4; i++) {
        int c  = c0 + ty + i * 8;   // KD-dim row of dst
        int rr = r0 + tx;           // N-dim col
        if (rr < N) dst[c * NMAX + rr] = tile[tx][ty + i * 8];
    }
}

__device__ __forceinline__ void cmpswap(float& a, float& b, bool up) {
    float mn = fminf(a, b), mx = fmaxf(a, b);
    a = up ? mn : mx;
    b = up ? mx : mn;
}

// ---------------- fused: column pair-sums + ALM + finalize ----------------
__global__ void __launch_bounds__(THREADS) fused_kernel(
    const float* __restrict__ s, const float* __restrict__ t,
    const void* __restrict__ rows_raw, const void* __restrict__ cols_raw,
    float* __restrict__ out, int Ns, int Nt, int nb)
{
    __shared__ float  ysort[PAD];
    __shared__ float  ypre[PAD + 1];   // shifted: ypre[0]=0, ypre[i+1]=incl prefix i
    __shared__ float  fwarp[16];
    __shared__ double dwarp[16];
    __shared__ int    slast;

    const int tid  = threadIdx.x;
    const int lane = tid & 31;
    const int wid  = tid >> 5;
    const int b    = blockIdx.x;

    if (b >= KD) {
        // ======== ALM blocks: anchor-pair L1 sums ========
        // coord = tid & 255 owns plane coordinate; tid>>8 splits the anchor slice.
        __shared__ int is64;
        if (tid == 0) {
            const int* r32 = (const int*)rows_raw;
            is64 = (r32[1] == 0 && r32[3] == 0 && r32[5] == 0) ? 1 : 0;
        }
        __syncthreads();
        const int a = b - KD;
        const int coord = tid & 255;
        const int half  = tid >> 8;
        const int chunk = (nb + ALM_BLOCKS - 1) / ALM_BLOCKS;
        const int lo = a * chunk, hi = min(nb, lo + chunk);
        const long long* r64 = (const long long*)rows_raw;
        const long long* c64 = (const long long*)cols_raw;
        const int* r32 = (const int*)rows_raw;
        const int* c32 = (const int*)cols_raw;
        double acc = 0.0;
        for (int bi = lo + half; bi < hi; bi += 2) {
            long long r = is64 ? r64[bi] : (long long)r32[bi];
            long long c = is64 ? c64[bi] : (long long)c32[bi];
            acc += (double)fabsf(s[r * KD + coord] - t[c * KD + coord]);
        }
        #pragma unroll
        for (int o = 16; o > 0; o >>= 1) acc += __shfl_down_sync(0xffffffffu, acc, o);
        if (lane == 0) dwarp[wid] = acc;
        __syncthreads();
        if (tid == 0) {
            #pragma unroll
            for (int k = 0; k < NRK; k++)
                g_almp[a * NRK + k] = dwarp[2 * k] + dwarp[2 * k + 1]
                                    + dwarp[8 + 2 * k] + dwarp[9 + 2 * k];
        }
    } else {
        // ======== column blocks: exact all-pairs L1 for plane coord b ========
        const float INF = __int_as_float(0x7f800000);
        const float* ycol = g_tT + (size_t)b * NMAX;
        const float* xcol = g_sT + (size_t)b * NMAX;
        const int base = tid * PER;

        // --- prefetch x early (latency hidden under the sort) ---
        float x[NX];
        bool  act[NX];
        #pragma unroll
        for (int u = 0; u < NX; u++) {
            act[u] = (tid + u * THREADS < Ns);
            x[u]   = xcol[tid + u * THREADS];   // in-bounds (padded), masked later
        }

        // --- load y column (aligned float4), mask pads with +inf ---
        float v[PER];
        {
            const float4 vy = *(const float4*)(ycol + base);
            v[0] = vy.x; v[1] = vy.y; v[2] = vy.z; v[3] = vy.w;
            #pragma unroll
            for (int m = 0; m < PER; m++)
                if (base + m >= Nt) v[m] = INF;
        }

        // --- phases k=2,4: sort own 4-chunk in registers ---
        {
            const bool asc = ((tid & 1) == 0);
            #pragma unroll
            for (int kk = 2; kk <= PER; kk <<= 1) {
                #pragma unroll
                for (int j = kk >> 1; j > 0; j >>= 1) {
                    #pragma unroll
                    for (int m = 0; m < PER; m++)
                        if ((m & j) == 0) {
                            bool up = (kk == PER) ? asc : ((m & kk) == 0);
                            cmpswap(v[m], v[m | j], up);
                        }
                }
            }
        }

        // --- phases k=8..2048: smem for j>=128, shfl for j=64..4, regs j=2,1 ---
        float4* sh4 = (float4*)ysort;
        #pragma unroll
        for (int k = 8; k <= PAD; k <<= 1) {
            const bool up = ((tid & (k >> 2)) == 0);
            // cross-warp steps via smem (one float4 per thread, conflict-free)
            #pragma unroll
            for (int j = k >> 1; j >= 128; j >>= 1) {
                const int jd = j >> 2;
                sh4[tid] = make_float4(v[0], v[1], v[2], v[3]);
                __syncthreads();
                const float4 o4 = sh4[tid ^ jd];
                const float o[PER] = {o4.x, o4.y, o4.z, o4.w};
                const bool keep_min = (((tid & jd) == 0) == up);
                #pragma unroll
                for (int m = 0; m < PER; m++)
                    v[m] = keep_min ? fminf(v[m], o[m]) : fmaxf(v[m], o[m]);
                __syncthreads();
            }
            // intra-warp steps via shfl
            #pragma unroll
            for (int j = ((k >> 1) < 64 ? (k >> 1) : 64); j >= PER; j >>= 1) {
                const int jd = j >> 2;
                const bool keep_min = (((tid & jd) == 0) == up);
                #pragma unroll
                for (int m = 0; m < PER; m++) {
                    float o = __shfl_xor_sync(0xffffffffu, v[m], jd);
                    v[m] = keep_min ? fminf(v[m], o) : fmaxf(v[m], o);
                }
            }
            // intra-thread steps j=2,1
            #pragma unroll
            for (int j = 2; j > 0; j >>= 1) {
                #pragma unroll
                for (int m = 0; m < PER; m++)
                    if ((m & j) == 0) cmpswap(v[m], v[m | j], up);
            }
        }

        // --- inclusive prefix scan (pads -> 0), regs + shfl ---
        float pre[PER];
        {
            float run = 0.f;
            #pragma unroll
            for (int m = 0; m < PER; m++) {
                float xv = (base + m < Nt) ? v[m] : 0.f;
                run += xv;
                pre[m] = run;
            }
            float incl = run;
            #pragma unroll
            for (int o = 1; o < 32; o <<= 1) {
                float n = __shfl_up_sync(0xffffffffu, incl, o);
                if (lane >= o) incl += n;
            }
            if (lane == 31) fwarp[wid] = incl;
            const float excl = incl - run;
            __syncthreads();
            float woff = 0.f;
            #pragma unroll
            for (int w = 0; w < 16; w++)
                if (w < wid) woff += fwarp[w];
            const float off = woff + excl;
            #pragma unroll
            for (int m = 0; m < PER; m++) pre[m] += off;
        }

        // publish sorted values + shifted prefix sums
        __syncthreads();  // ysort reuse safety
        sh4[tid] = make_float4(v[0], v[1], v[2], v[3]);
        #pragma unroll
        for (int m = 0; m < PER; m++) ypre[base + m + 1] = pre[m];
        if (tid == 0) ypre[0] = 0.f;
        __syncthreads();

        const float Ptot = ypre[Nt];

        // --- batched branchless binary search (NX independent chains) ---
        int pos[NX];
        #pragma unroll
        for (int u = 0; u < NX; u++) pos[u] = 0;
        #pragma unroll
        for (int step = PAD / 2; step >= 1; step >>= 1) {
            #pragma unroll
            for (int u = 0; u < NX; u++) {
                int c = pos[u] + step;
                if (ysort[c - 1] <= x[u]) pos[u] = c;  // pads +inf => pos <= Nt
            }
        }
        double acc = 0.0;
        #pragma unroll
        for (int u = 0; u < NX; u++) {
            float Pc = ypre[pos[u]];
            float contrib = x[u] * (float)(2 * pos[u] - Nt) + Ptot - 2.f * Pc;
            if (act[u]) acc += (double)contrib;
        }

        #pragma unroll
        for (int o = 16; o > 0; o >>= 1) acc += __shfl_down_sync(0xffffffffu, acc, o);
        if (lane == 0) dwarp[wid] = acc;
        __syncthreads();
        if (tid == 0) {
            double sum = 0.0;
            #pragma unroll
            for (int w = 0; w < 16; w++) sum += dwarp[w];
            g_col[b] = sum;
        }
    }

    // ======== completion ticket: last block finalizes ========
    if (tid == 0) {
        __threadfence();
        int tk = atomicAdd(&g_count, 1);
        slast = (tk == TOTAL_BLOCKS - 1) ? 1 : 0;
    }
    __syncthreads();
    if (!slast) return;
    __threadfence();

    // reduce g_col (256 doubles) by k-groups of 64
    double vv = (tid < KD) ? g_col[tid] : 0.0;
    #pragma unroll
    for (int o = 16; o > 0; o >>= 1) vv += __shfl_down_sync(0xffffffffu, vv, o);
    if (lane == 0) dwarp[wid] = vv;
    __syncthreads();
    if (tid == 0) {
        const double params[NRK] = {0.4, 0.2, 0.2, 0.2};
        const double EPS = 3.0;
        const double nb_notB = (double)Ns * (double)Nt - (double)nb;
        double ret = 0.0;
        #pragma unroll
        for (int k = 0; k < NRK; k++) {
            double all = dwarp[2 * k] + dwarp[2 * k + 1];
            double alm = 0.0;
            #pragma unroll
            for (int a = 0; a < ALM_BLOCKS; a++) alm += g_almp[a * NRK + k];
            double notalm = all - alm;
            double lk = alm * nb_notB + (EPS * nb_notB - notalm) * (double)nb;
            ret += params[k] * lk / (double)DW;
        }
        out[0] = (float)(ret / ((double)Ns * (double)Nt));
        g_count = 0;  // reset for next graph replay
    }
}

extern "C" void kernel_launch(void* const* d_in, const int* in_sizes, int n_in,
                              void* d_out, int out_size) {
    const float* s = (const float*)d_in[0];
    const float* t = (const float*)d_in[1];
    const void* rows = d_in[2];
    const void* cols = d_in[3];
    int Ns = in_sizes[0] / KD;
    int Nt = in_sizes[1] / KD;
    int nb = in_sizes[2];
    int nmax = Ns > Nt ? Ns : Nt;

    dim3 tgrid((nmax + 31) / 32, KD / 32, 2);
    dim3 tblk(32, 8, 1);
    transpose_kernel<<<tgrid, tblk>>>(s, t, Ns, Nt);
    fused_kernel<<<TOTAL_BLOCKS, THREADS>>>(s, t, rows, cols,
                                            (float*)d_out, Ns, Nt, nb);
}

// round 6
// speedup vs baseline: 1.2210x; 1.2210x over previous
#include <cuda_runtime.h>

#define NRK 4
#define DW  64
#define KD  256          // NR*D plane stride
#define PAD 2048         // power-of-2 pad for bitonic (Nt <= 2048)
#define THREADS 256
#define PER 8            // sort elements per thread (PAD/THREADS)
#define SPLIT 4          // search blocks per column
#define ALM_BLOCKS 16
#define NMAX 2048        // padded column stride
#define NCOLBLK (KD * SPLIT)            // 1024
#define TOTAL_B (NCOLBLK + ALM_BLOCKS)  // 1040

// Static scratch (no allocation). Zero-init at load; pads never written -> 0.
__device__ float  g_sT[KD * NMAX];           // s transposed+padded [KD][NMAX]
__device__ float  g_tT[KD * NMAX];           // t transposed+padded [KD][NMAX]
__device__ float  g_ys[KD * PAD];            // sorted y per column (+inf pads)
__device__ float  g_yp[KD * PAD];            // inclusive prefix per column
__device__ double g_colp[NCOLBLK];           // per-(col,split) partials
__device__ double g_almp[ALM_BLOCKS * NRK];  // per-block per-k anchor partials
__device__ int    g_count = 0;               // completion ticket (self-reset)

// ---------------- tiled transpose: [N][256] -> [256][NMAX] ----------------
__global__ void transpose_kernel(const float* __restrict__ s,
                                 const float* __restrict__ t,
                                 int Ns, int Nt) {
    __shared__ float tile[32][33];
    const float* src; float* dst; int N;
    if (blockIdx.z == 0) { src = s; dst = g_sT; N = Ns; }
    else                 { src = t; dst = g_tT; N = Nt; }
    const int tx = threadIdx.x, ty = threadIdx.y;  // 32 x 8
    const int r0 = blockIdx.x * 32, c0 = blockIdx.y * 32;
    #pragma unroll
    for (int i = 0; i < 4; i++) {
        int r = r0 + ty + i * 8;
        if (r < N) tile[ty + i * 8][tx] = src[r * KD + c0 + tx];
    }
    __syncthreads();
    #pragma unroll
    for (int i = 0; i < 4; i++) {
        int c  = c0 + ty + i * 8;
        int rr = r0 + tx;
        if (rr < N) dst[c * NMAX + rr] = tile[tx][ty + i * 8];
    }
}

__device__ __forceinline__ void cmpswap(float& a, float& b, bool up) {
    float mn = fminf(a, b), mx = fmaxf(a, b);
    a = up ? mn : mx;
    b = up ? mx : mn;
}

// ---------------- Phase A: per-column sort + prefix scan -> global ----------
__global__ void __launch_bounds__(THREADS) sort_kernel(int Nt) {
    __shared__ float ysort[PAD];
    __shared__ float fwarp[8];

    const int tid  = threadIdx.x;
    const int lane = tid & 31;
    const int wid  = tid >> 5;
    const int b    = blockIdx.x;
    const float INF = __int_as_float(0x7f800000);
    const float* ycol = g_tT + (size_t)b * NMAX;
    const int base = tid * PER;

    // aligned float4 loads, mask pads with +inf
    float v[PER];
    {
        float4 a0 = *(const float4*)(ycol + base);
        float4 a1 = *(const float4*)(ycol + base + 4);
        v[0]=a0.x; v[1]=a0.y; v[2]=a0.z; v[3]=a0.w;
        v[4]=a1.x; v[5]=a1.y; v[6]=a1.z; v[7]=a1.w;
        #pragma unroll
        for (int m = 0; m < PER; m++)
            if (base + m >= Nt) v[m] = INF;
    }

    // phases k=2,4,8 in registers
    {
        const bool asc = ((tid & 1) == 0);
        #pragma unroll
        for (int kk = 2; kk <= 8; kk <<= 1) {
            #pragma unroll
            for (int j = kk >> 1; j > 0; j >>= 1) {
                #pragma unroll
                for (int m = 0; m < PER; m++)
                    if ((m & j) == 0) {
                        bool up = (kk == 8) ? asc : ((m & kk) == 0);
                        cmpswap(v[m], v[m | j], up);
                    }
            }
        }
    }

    // phases k=16..2048: smem j>=256, shfl j=128..8, regs j=4,2,1
    float4* sh4 = (float4*)ysort;
    #pragma unroll
    for (int k = 16; k <= PAD; k <<= 1) {
        const bool up = ((tid & (k >> 3)) == 0);
        #pragma unroll
        for (int j = k >> 1; j >= 256; j >>= 1) {
            const int jd = j >> 3;
            sh4[tid * 2 + 0] = make_float4(v[0], v[1], v[2], v[3]);
            sh4[tid * 2 + 1] = make_float4(v[4], v[5], v[6], v[7]);
            __syncthreads();
            const int p = tid ^ jd;
            float4 oa = sh4[p * 2 + 0], ob = sh4[p * 2 + 1];
            float o[PER] = {oa.x, oa.y, oa.z, oa.w, ob.x, ob.y, ob.z, ob.w};
            const bool keep_min = (((tid & jd) == 0) == up);
            #pragma unroll
            for (int m = 0; m < PER; m++)
                v[m] = keep_min ? fminf(v[m], o[m]) : fmaxf(v[m], o[m]);
            __syncthreads();
        }
        #pragma unroll
        for (int j = ((k >> 1) < 128 ? (k >> 1) : 128); j >= 8; j >>= 1) {
            const int jd = j >> 3;
            const bool keep_min = (((tid & jd) == 0) == up);
            #pragma unroll
            for (int m = 0; m < PER; m++) {
                float o = __shfl_xor_sync(0xffffffffu, v[m], jd);
                v[m] = keep_min ? fminf(v[m], o) : fmaxf(v[m], o);
            }
        }
        #pragma unroll
        for (int j = 4; j > 0; j >>= 1) {
            #pragma unroll
            for (int m = 0; m < PER; m++)
                if ((m & j) == 0) cmpswap(v[m], v[m | j], up);
        }
    }

    // inclusive prefix scan (pads -> 0)
    float pre[PER];
    {
        float run = 0.f;
        #pragma unroll
        for (int m = 0; m < PER; m++) {
            float xv = (base + m < Nt) ? v[m] : 0.f;
            run += xv;
            pre[m] = run;
        }
        float incl = run;
        #pragma unroll
        for (int o = 1; o < 32; o <<= 1) {
            float n = __shfl_up_sync(0xffffffffu, incl, o);
            if (lane >= o) incl += n;
        }
        if (lane == 31) fwarp[wid] = incl;
        const float excl = incl - run;
        __syncthreads();
        float woff = 0.f;
        #pragma unroll
        for (int w = 0; w < 8; w++)
            if (w < wid) woff += fwarp[w];
        const float off = woff + excl;
        #pragma unroll
        for (int m = 0; m < PER; m++) pre[m] += off;
    }

    // coalesced float4 stores of sorted values + inclusive prefix
    float* ysg = g_ys + (size_t)b * PAD;
    float* ypg = g_yp + (size_t)b * PAD;
    *(float4*)(ysg + base)     = make_float4(v[0], v[1], v[2], v[3]);
    *(float4*)(ysg + base + 4) = make_float4(v[4], v[5], v[6], v[7]);
    *(float4*)(ypg + base)     = make_float4(pre[0], pre[1], pre[2], pre[3]);
    *(float4*)(ypg + base + 4) = make_float4(pre[4], pre[5], pre[6], pre[7]);
}

// ---------------- Phase B: search (+ALM) + ticket finalize ----------------
#define NX 2
__global__ void __launch_bounds__(THREADS) search_kernel(
    const float* __restrict__ s, const float* __restrict__ t,
    const void* __restrict__ rows_raw, const void* __restrict__ cols_raw,
    float* __restrict__ out, int Ns, int Nt, int nb)
{
    __shared__ float  ys[PAD];
    __shared__ float  yp[PAD + 1];
    __shared__ double dwarp[8];
    __shared__ int    slast;

    const int tid  = threadIdx.x;
    const int lane = tid & 31;
    const int wid  = tid >> 5;
    const int b    = blockIdx.x;

    if (b >= NCOLBLK) {
        // ---- ALM blocks ----
        __shared__ int is64;
        if (tid == 0) {
            const int* r32 = (const int*)rows_raw;
            is64 = (r32[1] == 0 && r32[3] == 0 && r32[5] == 0) ? 1 : 0;
        }
        __syncthreads();
        const int a = b - NCOLBLK;
        const int chunk = (nb + ALM_BLOCKS - 1) / ALM_BLOCKS;
        const int lo = a * chunk, hi = min(nb, lo + chunk);
        const long long* r64 = (const long long*)rows_raw;
        const long long* c64 = (const long long*)cols_raw;
        const int* r32 = (const int*)rows_raw;
        const int* c32 = (const int*)cols_raw;
        double acc = 0.0;
        for (int bi = lo; bi < hi; bi++) {
            long long r = is64 ? r64[bi] : (long long)r32[bi];
            long long c = is64 ? c64[bi] : (long long)c32[bi];
            acc += (double)fabsf(s[r * KD + tid] - t[c * KD + tid]);
        }
        #pragma unroll
        for (int o = 16; o > 0; o >>= 1) acc += __shfl_down_sync(0xffffffffu, acc, o);
        if (lane == 0) dwarp[wid] = acc;
        __syncthreads();
        if (tid == 0) {
            #pragma unroll
            for (int k = 0; k < NRK; k++)
                g_almp[a * NRK + k] = dwarp[2 * k] + dwarp[2 * k + 1];
        }
    } else {
        // ---- column-chunk search blocks ----
        const int col = b >> 2;       // b / SPLIT
        const int spl = b & (SPLIT - 1);
        const int chunk = (Ns + SPLIT - 1) / SPLIT;
        const int xlo = spl * chunk;
        const float* ysg = g_ys + (size_t)col * PAD;
        const float* ypg = g_yp + (size_t)col * PAD;
        const float* xcol = g_sT + (size_t)col * NMAX;

        // prefetch x
        float x[NX];
        bool  act[NX];
        #pragma unroll
        for (int u = 0; u < NX; u++) {
            int i = xlo + tid + u * THREADS;
            act[u] = (i < Ns) && (i < xlo + chunk);
            x[u]   = xcol[min(i, NMAX - 1)];
        }

        // load sorted column + shifted prefix into smem (coalesced)
        {
            const float4* s4 = (const float4*)ysg;
            float4* d4 = (float4*)ys;
            d4[tid]           = s4[tid];
            d4[tid + THREADS] = s4[tid + THREADS];
            #pragma unroll
            for (int r = 0; r < PAD / THREADS; r++) {
                int i = tid + r * THREADS;
                yp[i + 1] = ypg[i];
            }
            if (tid == 0) yp[0] = 0.f;
        }
        __syncthreads();

        const float Ptot = yp[Nt];

        int pos[NX];
        #pragma unroll
        for (int u = 0; u < NX; u++) pos[u] = 0;
        #pragma unroll
        for (int step = PAD / 2; step >= 1; step >>= 1) {
            #pragma unroll
            for (int u = 0; u < NX; u++) {
                int c = pos[u] + step;
                if (ys[c - 1] <= x[u]) pos[u] = c;   // +inf pads => pos <= Nt
            }
        }
        double acc = 0.0;
        #pragma unroll
        for (int u = 0; u < NX; u++) {
            float Pc = yp[pos[u]];
            float contrib = x[u] * (float)(2 * pos[u] - Nt) + Ptot - 2.f * Pc;
            if (act[u]) acc += (double)contrib;
        }
        #pragma unroll
        for (int o = 16; o > 0; o >>= 1) acc += __shfl_down_sync(0xffffffffu, acc, o);
        if (lane == 0) dwarp[wid] = acc;
        __syncthreads();
        if (tid == 0) {
            double sum = 0.0;
            #pragma unroll
            for (int w = 0; w < 8; w++) sum += dwarp[w];
            g_colp[b] = sum;
        }
    }

    // ---- completion ticket: last block finalizes ----
    if (tid == 0) {
        __threadfence();
        int tk = atomicAdd(&g_count, 1);
        slast = (tk == TOTAL_B - 1) ? 1 : 0;
    }
    __syncthreads();
    if (!slast) return;
    __threadfence();

    // per-column totals: thread tid = column, sum its SPLIT partials
    double vv = 0.0;
    #pragma unroll
    for (int u = 0; u < SPLIT; u++) vv += g_colp[tid * SPLIT + u];
    #pragma unroll
    for (int o = 16; o > 0; o >>= 1) vv += __shfl_down_sync(0xffffffffu, vv, o);
    if (lane == 0) dwarp[wid] = vv;
    __syncthreads();
    if (tid == 0) {
        const double params[NRK] = {0.4, 0.2, 0.2, 0.2};
        const double EPS = 3.0;
        const double nb_notB = (double)Ns * (double)Nt - (double)nb;
        double ret = 0.0;
        #pragma unroll
        for (int k = 0; k < NRK; k++) {
            double all = dwarp[2 * k] + dwarp[2 * k + 1];
            double alm = 0.0;
            #pragma unroll
            for (int a = 0; a < ALM_BLOCKS; a++) alm += g_almp[a * NRK + k];
            double notalm = all - alm;
            double lk = alm * nb_notB + (EPS * nb_notB - notalm) * (double)nb;
            ret += params[k] * lk / (double)DW;
        }
        out[0] = (float)(ret / ((double)Ns * (double)Nt));
        g_count = 0;  // reset for next graph replay
    }
}

extern "C" void kernel_launch(void* const* d_in, const int* in_sizes, int n_in,
                              void* d_out, int out_size) {
    const float* s = (const float*)d_in[0];
    const float* t = (const float*)d_in[1];
    const void* rows = d_in[2];
    const void* cols = d_in[3];
    int Ns = in_sizes[0] / KD;
    int Nt = in_sizes[1] / KD;
    int nb = in_sizes[2];
    int nmax = Ns > Nt ? Ns : Nt;

    dim3 tgrid((nmax + 31) / 32, KD / 32, 2);
    dim3 tblk(32, 8, 1);
    transpose_kernel<<<tgrid, tblk>>>(s, t, Ns, Nt);
    sort_kernel<<<KD, THREADS>>>(Nt);
    search_kernel<<<TOTAL_B, THREADS>>>(s, t, rows, cols,
                                        (float*)d_out, Ns, Nt, nb);
}

// round 7
// speedup vs baseline: 1.2636x; 1.0349x over previous
#include <cuda_runtime.h>

#define NRK 4
#define DW  64
#define KD  256          // NR*D plane stride
#define PAD 2048         // power-of-2 pad for bitonic (Nt <= 2048)
#define THREADS 256
#define PER 8            // sort elements per thread (PAD/THREADS)
#define SPLIT 2          // blocks per column (redundant sort, split search)
#define NX  4            // search slots per thread (THREADS*NX >= Ns/SPLIT)
#define ALM_BLOCKS 8
#define NMAX 2048        // padded column stride
#define NCOLBLK (KD * SPLIT)               // 512
#define TOTAL_BLOCKS (NCOLBLK + ALM_BLOCKS)

// Static scratch (no allocation). Zero-init at load; pads never written -> 0.
__device__ float  g_sT[KD * NMAX];           // s transposed+padded: [KD][NMAX]
__device__ float  g_tT[KD * NMAX];           // t transposed+padded: [KD][NMAX]
__device__ double g_colp[NCOLBLK];           // per-(col,half) partials
__device__ double g_almp[ALM_BLOCKS * NRK];  // per-block per-k anchor partials
__device__ int    g_count = 0;               // completion ticket (self-reset)

// ---------------- tiled transpose: [N][256] -> [256][NMAX] ----------------
__global__ void transpose_kernel(const float* __restrict__ s,
                                 const float* __restrict__ t,
                                 int Ns, int Nt) {
    __shared__ float tile[32][33];
    const float* src; float* dst; int N;
    if (blockIdx.z == 0) { src = s; dst = g_sT; N = Ns; }
    else                 { src = t; dst = g_tT; N = Nt; }
    const int tx = threadIdx.x, ty = threadIdx.y;  // 32 x 8
    const int r0 = blockIdx.x * 32, c0 = blockIdx.y * 32;
    #pragma unroll
    for (int i = 0; i < 4; i++) {
        int r = r0 + ty + i * 8;
        if (r < N) tile[ty + i * 8][tx] = src[r * KD + c0 + tx];
    }
    __syncthreads();
    #pragma unroll
    for (int i = 0; i < 4; i++) {
        int c  = c0 + ty + i * 8;
        int rr = r0 + tx;
        if (rr < N) dst[c * NMAX + rr] = tile[tx][ty + i * 8];
    }
}

__device__ __forceinline__ void cmpswap(float& a, float& b, bool up) {
    float mn = fminf(a, b), mx = fmaxf(a, b);
    a = up ? mn : mx;
    b = up ? mx : mn;
}

// ---------------- fused: column pair-sums + ALM + finalize ----------------
__global__ void __launch_bounds__(THREADS) fused_kernel(
    const float* __restrict__ s, const float* __restrict__ t,
    const void* __restrict__ rows_raw, const void* __restrict__ cols_raw,
    float* __restrict__ out, int Ns, int Nt, int nb)
{
    __shared__ float  ysort[PAD];
    __shared__ float  ypre[PAD + 1];   // shifted: ypre[0]=0, ypre[i+1]=incl prefix i
    __shared__ float  fwarp[8];
    __shared__ double dwarp[8];
    __shared__ int    slast;

    const int tid  = threadIdx.x;
    const int lane = tid & 31;
    const int wid  = tid >> 5;
    const int b    = blockIdx.x;

    if (b >= NCOLBLK) {
        // ======== ALM blocks: anchor-pair L1 sums, sliced over anchors ========
        __shared__ int is64;
        if (tid == 0) {
            const int* r32 = (const int*)rows_raw;
            is64 = (r32[1] == 0 && r32[3] == 0 && r32[5] == 0) ? 1 : 0;
        }
        __syncthreads();
        const int a = b - NCOLBLK;
        const int chunk = (nb + ALM_BLOCKS - 1) / ALM_BLOCKS;
        const int lo = a * chunk, hi = min(nb, lo + chunk);
        const long long* r64 = (const long long*)rows_raw;
        const long long* c64 = (const long long*)cols_raw;
        const int* r32 = (const int*)rows_raw;
        const int* c32 = (const int*)cols_raw;
        double acc = 0.0;
        for (int bi = lo; bi < hi; bi++) {
            long long r = is64 ? r64[bi] : (long long)r32[bi];
            long long c = is64 ? c64[bi] : (long long)c32[bi];
            acc += (double)fabsf(s[r * KD + tid] - t[c * KD + tid]);
        }
        #pragma unroll
        for (int o = 16; o > 0; o >>= 1) acc += __shfl_down_sync(0xffffffffu, acc, o);
        if (lane == 0) dwarp[wid] = acc;
        __syncthreads();
        if (tid == 0) {
            #pragma unroll
            for (int k = 0; k < NRK; k++)
                g_almp[a * NRK + k] = dwarp[2 * k] + dwarp[2 * k + 1];
        }
    } else {
        // ======== column blocks: redundant sort, split search ========
        const int col  = b >> 1;         // column index
        const int half = b & 1;          // which half of x's to search
        const float INF = __int_as_float(0x7f800000);
        const float* ycol = g_tT + (size_t)col * NMAX;
        const float* xcol = g_sT + (size_t)col * NMAX;
        const int base = tid * PER;

        const int chunk = (Ns + SPLIT - 1) / SPLIT;
        const int xlo = half * chunk;
        const int xhi = min(Ns, xlo + chunk);

        // --- prefetch x early (latency hidden under the sort) ---
        float x[NX];
        bool  act[NX];
        #pragma unroll
        for (int u = 0; u < NX; u++) {
            int i = xlo + tid + u * THREADS;
            act[u] = (i < xhi);
            x[u]   = xcol[min(i, NMAX - 1)];   // in-bounds (padded), masked later
        }

        // --- load y column (aligned float4), mask pads with +inf ---
        float v[PER];
        {
            float4 a0 = *(const float4*)(ycol + base);
            float4 a1 = *(const float4*)(ycol + base + 4);
            v[0]=a0.x; v[1]=a0.y; v[2]=a0.z; v[3]=a0.w;
            v[4]=a1.x; v[5]=a1.y; v[6]=a1.z; v[7]=a1.w;
            #pragma unroll
            for (int m = 0; m < PER; m++)
                if (base + m >= Nt) v[m] = INF;
        }

        // --- phases k=2,4,8: sort own 8-chunk in registers ---
        {
            const bool asc = ((tid & 1) == 0);
            #pragma unroll
            for (int kk = 2; kk <= 8; kk <<= 1) {
                #pragma unroll
                for (int j = kk >> 1; j > 0; j >>= 1) {
                    #pragma unroll
                    for (int m = 0; m < PER; m++)
                        if ((m & j) == 0) {
                            bool up = (kk == 8) ? asc : ((m & kk) == 0);
                            cmpswap(v[m], v[m | j], up);
                        }
                }
            }
        }

        // --- phases k=16..2048: smem j>=256, shfl j=128..8, regs j=4,2,1 ---
        float4* sh4 = (float4*)ysort;
        #pragma unroll
        for (int k = 16; k <= PAD; k <<= 1) {
            const bool up = ((tid & (k >> 3)) == 0);
            #pragma unroll
            for (int j = k >> 1; j >= 256; j >>= 1) {
                const int jd = j >> 3;
                sh4[tid * 2 + 0] = make_float4(v[0], v[1], v[2], v[3]);
                sh4[tid * 2 + 1] = make_float4(v[4], v[5], v[6], v[7]);
                __syncthreads();
                const int p = tid ^ jd;
                float4 oa = sh4[p * 2 + 0], ob = sh4[p * 2 + 1];
                float o[PER] = {oa.x, oa.y, oa.z, oa.w, ob.x, ob.y, ob.z, ob.w};
                const bool keep_min = (((tid & jd) == 0) == up);
                #pragma unroll
                for (int m = 0; m < PER; m++)
                    v[m] = keep_min ? fminf(v[m], o[m]) : fmaxf(v[m], o[m]);
                __syncthreads();
            }
            #pragma unroll
            for (int j = ((k >> 1) < 128 ? (k >> 1) : 128); j >= 8; j >>= 1) {
                const int jd = j >> 3;
                const bool keep_min = (((tid & jd) == 0) == up);
                #pragma unroll
                for (int m = 0; m < PER; m++) {
                    float o = __shfl_xor_sync(0xffffffffu, v[m], jd);
                    v[m] = keep_min ? fminf(v[m], o) : fmaxf(v[m], o);
                }
            }
            #pragma unroll
            for (int j = 4; j > 0; j >>= 1) {
                #pragma unroll
                for (int m = 0; m < PER; m++)
                    if ((m & j) == 0) cmpswap(v[m], v[m | j], up);
            }
        }

        // --- inclusive prefix scan (pads -> 0), regs + shfl ---
        float pre[PER];
        {
            float run = 0.f;
            #pragma unroll
            for (int m = 0; m < PER; m++) {
                float xv = (base + m < Nt) ? v[m] : 0.f;
                run += xv;
                pre[m] = run;
            }
            float incl = run;
            #pragma unroll
            for (int o = 1; o < 32; o <<= 1) {
                float n = __shfl_up_sync(0xffffffffu, incl, o);
                if (lane >= o) incl += n;
            }
            if (lane == 31) fwarp[wid] = incl;
            const float excl = incl - run;
            __syncthreads();
            float woff = 0.f;
            #pragma unroll
            for (int w = 0; w < 8; w++)
                if (w < wid) woff += fwarp[w];
            const float off = woff + excl;
            #pragma unroll
            for (int m = 0; m < PER; m++) pre[m] += off;
        }

        // publish sorted values + shifted prefix sums
        __syncthreads();  // ysort reuse safety
        sh4[tid * 2 + 0] = make_float4(v[0], v[1], v[2], v[3]);
        sh4[tid * 2 + 1] = make_float4(v[4], v[5], v[6], v[7]);
        #pragma unroll
        for (int m = 0; m < PER; m++) ypre[base + m + 1] = pre[m];
        if (tid == 0) ypre[0] = 0.f;
        __syncthreads();

        const float Ptot = ypre[Nt];

        // --- batched branchless binary search (NX independent chains) ---
        int pos[NX];
        #pragma unroll
        for (int u = 0; u < NX; u++) pos[u] = 0;
        #pragma unroll
        for (int step = PAD / 2; step >= 1; step >>= 1) {
            #pragma unroll
            for (int u = 0; u < NX; u++) {
                int c = pos[u] + step;
                if (ysort[c - 1] <= x[u]) pos[u] = c;  // pads +inf => pos <= Nt
            }
        }
        double acc = 0.0;
        #pragma unroll
        for (int u = 0; u < NX; u++) {
            float Pc = ypre[pos[u]];
            float contrib = x[u] * (float)(2 * pos[u] - Nt) + Ptot - 2.f * Pc;
            if (act[u]) acc += (double)contrib;
        }

        #pragma unroll
        for (int o = 16; o > 0; o >>= 1) acc += __shfl_down_sync(0xffffffffu, acc, o);
        if (lane == 0) dwarp[wid] = acc;
        __syncthreads();
        if (tid == 0) {
            double sum = 0.0;
            #pragma unroll
            for (int w = 0; w < 8; w++) sum += dwarp[w];
            g_colp[b] = sum;
        }
    }

    // ======== completion ticket: last block finalizes ========
    if (tid == 0) {
        __threadfence();
        int tk = atomicAdd(&g_count, 1);
        slast = (tk == TOTAL_BLOCKS - 1) ? 1 : 0;
    }
    __syncthreads();
    if (!slast) return;
    __threadfence();

    // per-column totals: thread tid = column, sum its SPLIT partials
    double vv = 0.0;
    #pragma unroll
    for (int u = 0; u < SPLIT; u++) vv += g_colp[tid * SPLIT + u];
    #pragma unroll
    for (int o = 16; o > 0; o >>= 1) vv += __shfl_down_sync(0xffffffffu, vv, o);
    if (lane == 0) dwarp[wid] = vv;
    __syncthreads();
    if (tid == 0) {
        const double params[NRK] = {0.4, 0.2, 0.2, 0.2};
        const double EPS = 3.0;
        const double nb_notB = (double)Ns * (double)Nt - (double)nb;
        double ret = 0.0;
        #pragma unroll
        for (int k = 0; k < NRK; k++) {
            double all = dwarp[2 * k] + dwarp[2 * k + 1];
            double alm = 0.0;
            #pragma unroll
            for (int a = 0; a < ALM_BLOCKS; a++) alm += g_almp[a * NRK + k];
            double notalm = all - alm;
            double lk = alm * nb_notB + (EPS * nb_notB - notalm) * (double)nb;
            ret += params[k] * lk / (double)DW;
        }
        out[0] = (float)(ret / ((double)Ns * (double)Nt));
        g_count = 0;  // reset for next graph replay
    }
}

extern "C" void kernel_launch(void* const* d_in, const int* in_sizes, int n_in,
                              void* d_out, int out_size) {
    const float* s = (const float*)d_in[0];
    const float* t = (const float*)d_in[1];
    const void* rows = d_in[2];
    const void* cols = d_in[3];
    int Ns = in_sizes[0] / KD;
    int Nt = in_sizes[1] / KD;
    int nb = in_sizes[2];
    int nmax = Ns > Nt ? Ns : Nt;

    dim3 tgrid((nmax + 31) / 32, KD / 32, 2);
    dim3 tblk(32, 8, 1);
    transpose_kernel<<<tgrid, tblk>>>(s, t, Ns, Nt);
    fused_kernel<<<TOTAL_BLOCKS, THREADS>>>(s, t, rows, cols,
                                            (float*)d_out, Ns, Nt, nb);
}

// round 8
// speedup vs baseline: 1.9310x; 1.5282x over previous
#include <cuda_runtime.h>

#define NRK 4
#define DW  64
#define KD  256            // NR*D plane stride
#define THREADS 256
#define NB  512            // value buckets
#define YS  8              // y slots per thread (Nt <= 2048)
#define XS  8              // x slots per thread (Ns <= 2048)
#define ALM_BLOCKS 8
#define NMAX 2048          // padded column stride
#define TOTAL_BLOCKS (KD + ALM_BLOCKS)

// Static scratch (no allocation). Zero-init at load; pads never written -> 0.
__device__ float  g_sT[KD * NMAX];           // s transposed+padded: [KD][NMAX]
__device__ float  g_tT[KD * NMAX];           // t transposed+padded: [KD][NMAX]
__device__ double g_colp[KD];                // per-column partials
__device__ double g_almp[ALM_BLOCKS * NRK];  // per-block per-k anchor partials
__device__ int    g_count = 0;               // completion ticket (self-reset)

// ---------------- tiled transpose: [N][256] -> [256][NMAX] ----------------
__global__ void transpose_kernel(const float* __restrict__ s,
                                 const float* __restrict__ t,
                                 int Ns, int Nt) {
    __shared__ float tile[32][33];
    const float* src; float* dst; int N;
    if (blockIdx.z == 0) { src = s; dst = g_sT; N = Ns; }
    else                 { src = t; dst = g_tT; N = Nt; }
    const int tx = threadIdx.x, ty = threadIdx.y;  // 32 x 8
    const int r0 = blockIdx.x * 32, c0 = blockIdx.y * 32;
    #pragma unroll
    for (int i = 0; i < 4; i++) {
        int r = r0 + ty + i * 8;
        if (r < N) tile[ty + i * 8][tx] = src[r * KD + c0 + tx];
    }
    __syncthreads();
    #pragma unroll
    for (int i = 0; i < 4; i++) {
        int c  = c0 + ty + i * 8;
        int rr = r0 + tx;
        if (rr < N) dst[c * NMAX + rr] = tile[tx][ty + i * 8];
    }
}

// monotone value -> bucket map: linear over [-4,4], clamped
__device__ __forceinline__ int bucket_of(float v) {
    int bi = __float2int_rd(v * 64.0f + 256.0f);   // NB/8 = 64 buckets per unit
    return min(max(bi, 0), NB - 1);
}

// ---------------- fused: bucket counting-sort pair-sums + ALM + finalize ----
__global__ void __launch_bounds__(THREADS) fused_kernel(
    const float* __restrict__ s, const float* __restrict__ t,
    const void* __restrict__ rows_raw, const void* __restrict__ cols_raw,
    float* __restrict__ out, int Ns, int Nt, int nb)
{
    __shared__ float  ysc[NMAX];      // y scattered in bucket order (Nt entries)
    __shared__ int    bcnt[NB + 1];   // histogram -> exclusive prefix counts
    __shared__ float  bsum[NB + 1];   // per-bucket sums -> exclusive prefix
    __shared__ int    boff[NB];       // scatter cursors
    __shared__ int    iwarp[8];
    __shared__ float  fwarp[8];
    __shared__ double dwarp[8];
    __shared__ int    slast;

    const int tid  = threadIdx.x;
    const int lane = tid & 31;
    const int wid  = tid >> 5;
    const int b    = blockIdx.x;

    if (b >= KD) {
        // ======== ALM blocks: anchor-pair L1 sums, sliced over anchors ========
        __shared__ int is64;
        if (tid == 0) {
            const int* r32 = (const int*)rows_raw;
            is64 = (r32[1] == 0 && r32[3] == 0 && r32[5] == 0) ? 1 : 0;
        }
        __syncthreads();
        const int a = b - KD;
        const int chunk = (nb + ALM_BLOCKS - 1) / ALM_BLOCKS;
        const int lo = a * chunk, hi = min(nb, lo + chunk);
        const long long* r64 = (const long long*)rows_raw;
        const long long* c64 = (const long long*)cols_raw;
        const int* r32 = (const int*)rows_raw;
        const int* c32 = (const int*)cols_raw;
        double acc = 0.0;
        for (int bi = lo; bi < hi; bi++) {
            long long r = is64 ? r64[bi] : (long long)r32[bi];
            long long c = is64 ? c64[bi] : (long long)c32[bi];
            acc += (double)fabsf(s[r * KD + tid] - t[c * KD + tid]);
        }
        #pragma unroll
        for (int o = 16; o > 0; o >>= 1) acc += __shfl_down_sync(0xffffffffu, acc, o);
        if (lane == 0) dwarp[wid] = acc;
        __syncthreads();
        if (tid == 0) {
            #pragma unroll
            for (int k = 0; k < NRK; k++)
                g_almp[a * NRK + k] = dwarp[2 * k] + dwarp[2 * k + 1];
        }
    } else {
        // ======== column blocks: exact all-pairs L1 via bucket counting ======
        const float* ycol = g_tT + (size_t)b * NMAX;
        const float* xcol = g_sT + (size_t)b * NMAX;

        // zero histogram
        #pragma unroll
        for (int r = 0; r < (NB + THREADS) / THREADS; r++) {
            int i = tid + r * THREADS;
            if (i <= NB) { bcnt[i] = 0; bsum[i] = 0.f; }
        }

        // prefetch x early (latency overlaps histogram phase)
        float x[XS];
        bool  xact[XS];
        #pragma unroll
        for (int u = 0; u < XS; u++) {
            int i = tid + u * THREADS;
            xact[u] = (i < Ns);
            x[u]    = xcol[min(i, NMAX - 1)];
        }
        __syncthreads();

        // load y, histogram counts + sums
        float yv[YS];
        int   ybi[YS];
        bool  yact[YS];
        #pragma unroll
        for (int u = 0; u < YS; u++) {
            int j = tid + u * THREADS;
            yact[u] = (j < Nt);
            if (yact[u]) {
                float v = ycol[j];
                int bi = bucket_of(v);
                yv[u] = v; ybi[u] = bi;
                atomicAdd(&bcnt[bi], 1);
                atomicAdd(&bsum[bi], v);
            }
        }
        __syncthreads();

        // exclusive scan of 512 buckets (counts + sums): 2 per thread + shfl
        {
            int   c0 = bcnt[2 * tid], c1 = bcnt[2 * tid + 1];
            float s0 = bsum[2 * tid], s1 = bsum[2 * tid + 1];
            int   tc = c0 + c1;
            float ts = s0 + s1;
            int   ci = tc;
            float si = ts;
            #pragma unroll
            for (int o = 1; o < 32; o <<= 1) {
                int   nc = __shfl_up_sync(0xffffffffu, ci, o);
                float nsv = __shfl_up_sync(0xffffffffu, si, o);
                if (lane >= o) { ci += nc; si += nsv; }
            }
            if (lane == 31) { iwarp[wid] = ci; fwarp[wid] = si; }
            __syncthreads();
            int   coff = 0;
            float soff = 0.f;
            #pragma unroll
            for (int w = 0; w < 8; w++)
                if (w < wid) { coff += iwarp[w]; soff += fwarp[w]; }
            const int   cbase = coff + ci - tc;
            const float sbase = soff + si - ts;
            __syncthreads();   // all reads of bcnt/bsum done before overwrite
            bcnt[2 * tid]     = cbase;
            bcnt[2 * tid + 1] = cbase + c0;
            bsum[2 * tid]     = sbase;
            bsum[2 * tid + 1] = sbase + s0;
            boff[2 * tid]     = cbase;
            boff[2 * tid + 1] = cbase + c0;
            if (tid == THREADS - 1) {
                bcnt[NB] = cbase + tc;   // = Nt
                bsum[NB] = sbase + ts;   // = Ptot
            }
        }
        __syncthreads();

        // scatter y into bucket order
        #pragma unroll
        for (int u = 0; u < YS; u++) {
            if (yact[u]) {
                int p = atomicAdd(&boff[ybi[u]], 1);
                ysc[p] = yv[u];
            }
        }
        __syncthreads();

        const float Ptot = bsum[NB];

        // per-x: prefix from bucket table + exact partial-bucket scan
        double acc = 0.0;
        #pragma unroll
        for (int u = 0; u < XS; u++) {
            if (!xact[u]) continue;
            const float xv = x[u];
            const int bx  = bucket_of(xv);
            const int beg = bcnt[bx];
            const int end = bcnt[bx + 1];
            int   c = beg;
            float P = bsum[bx];
            for (int idx = beg; idx < end; idx++) {
                float yy = ysc[idx];
                if (yy <= xv) { c++; P += yy; }
            }
            acc += (double)(xv * (float)(2 * c - Nt) + Ptot - 2.f * P);
        }

        #pragma unroll
        for (int o = 16; o > 0; o >>= 1) acc += __shfl_down_sync(0xffffffffu, acc, o);
        if (lane == 0) dwarp[wid] = acc;
        __syncthreads();
        if (tid == 0) {
            double sum = 0.0;
            #pragma unroll
            for (int w = 0; w < 8; w++) sum += dwarp[w];
            g_colp[b] = sum;
        }
    }

    // ======== completion ticket: last block finalizes ========
    if (tid == 0) {
        __threadfence();
        int tk = atomicAdd(&g_count, 1);
        slast = (tk == TOTAL_BLOCKS - 1) ? 1 : 0;
    }
    __syncthreads();
    if (!slast) return;
    __threadfence();

    // reduce g_colp (256 doubles) by k-groups of 64
    double vv = g_colp[tid];
    #pragma unroll
    for (int o = 16; o > 0; o >>= 1) vv += __shfl_down_sync(0xffffffffu, vv, o);
    if (lane == 0) dwarp[wid] = vv;
    __syncthreads();
    if (tid == 0) {
        const double params[NRK] = {0.4, 0.2, 0.2, 0.2};
        const double EPS = 3.0;
        const double nb_notB = (double)Ns * (double)Nt - (double)nb;
        double ret = 0.0;
        #pragma unroll
        for (int k = 0; k < NRK; k++) {
            double all = dwarp[2 * k] + dwarp[2 * k + 1];
            double alm = 0.0;
            #pragma unroll
            for (int a = 0; a < ALM_BLOCKS; a++) alm += g_almp[a * NRK + k];
            double notalm = all - alm;
            double lk = alm * nb_notB + (EPS * nb_notB - notalm) * (double)nb;
            ret += params[k] * lk / (double)DW;
        }
        out[0] = (float)(ret / ((double)Ns * (double)Nt));
        g_count = 0;  // reset for next graph replay
    }
}

extern "C" void kernel_launch(void* const* d_in, const int* in_sizes, int n_in,
                              void* d_out, int out_size) {
    const float* s = (const float*)d_in[0];
    const float* t = (const float*)d_in[1];
    const void* rows = d_in[2];
    const void* cols = d_in[3];
    int Ns = in_sizes[0] / KD;
    int Nt = in_sizes[1] / KD;
    int nb = in_sizes[2];
    int nmax = Ns > Nt ? Ns : Nt;

    dim3 tgrid((nmax + 31) / 32, KD / 32, 2);
    dim3 tblk(32, 8, 1);
    transpose_kernel<<<tgrid, tblk>>>(s, t, Ns, Nt);
    fused_kernel<<<TOTAL_BLOCKS, THREADS>>>(s, t, rows, cols,
                                            (float*)d_out, Ns, Nt, nb);
}